// round 1
// baseline (speedup 1.0000x reference)
#include <cuda_runtime.h>
#include <cuda_bf16.h>

#define Bb 2
#define Cc 256
#define Hh 48
#define Nn 110592        // 48*48*48
#define PLANE 2304       // 48*48
#define NH 4
#define DV 64
#define DQK 32
#define QKD 128
#define EPSILON 1e-6f

// -------- scratch (static device globals; no allocation at runtime) --------
__device__ __align__(16) float g_qk[(size_t)Bb * Cc * Nn];   // rows 0..127 = q logits, 128..255 = k logits
__device__ __align__(16) float g_v[(size_t)Bb * Cc * Nn];    // depthwise conv output
__device__ float g_kv[Bb * NH * DQK * DV];                   // unnormalized kv
__device__ float g_s[Bb * NH * DQK];                         // sum of exp(k) per dk row
__device__ float g_kvn[Bb * NH * DQK * DV];                  // normalized kv

// ======================= K1: qk GEMM ===========================
// qk[b][o][n] = sum_c W[o][c] * x[b][c][n]; W = Wq (o<128) / Wk (o>=128)
// Tiles: BM=128 (o), BN=128 (n), BK=16, 256 threads, 8x8 microtile.
#define BM 128
#define BN 128
#define BK 16

__global__ __launch_bounds__(256) void k_gemm_qk(const float* __restrict__ x,
                                                 const float* __restrict__ Wq,
                                                 const float* __restrict__ Wk) {
    __shared__ float Wts[BM][BK + 4];   // row stride 20 floats = 80B (16B aligned)
    __shared__ float Xts[BK][BN];

    const int b  = blockIdx.z;
    const int o0 = blockIdx.y * BM;       // 0 or 128
    const int n0 = blockIdx.x * BN;
    const float* Wsrc = (blockIdx.y == 0) ? Wq : Wk;
    const float* xb = x + (size_t)b * Cc * Nn;

    const int tid = threadIdx.x;
    const int tx = tid & 15;   // n sub-tile
    const int ty = tid >> 4;   // o sub-tile

    float acc[8][8];
#pragma unroll
    for (int i = 0; i < 8; i++)
#pragma unroll
        for (int j = 0; j < 8; j++) acc[i][j] = 0.f;

    for (int k0 = 0; k0 < Cc; k0 += BK) {
        __syncthreads();
        // load W tile: 128 rows x 16 cols = 512 float4, 2 per thread
#pragma unroll
        for (int u = 0; u < 2; u++) {
            int idx = u * 256 + tid;
            int r = idx >> 2, cq = idx & 3;
            float4 w4 = *(const float4*)(Wsrc + (size_t)r * Cc + k0 + cq * 4);
            *(float4*)&Wts[r][cq * 4] = w4;
        }
        // load X tile: 16 rows x 128 cols = 512 float4, 2 per thread (coalesced)
#pragma unroll
        for (int u = 0; u < 2; u++) {
            int idx = u * 256 + tid;
            int r = idx >> 5, cq = idx & 31;
            float4 v4 = *(const float4*)(xb + (size_t)(k0 + r) * Nn + n0 + cq * 4);
            *(float4*)&Xts[r][cq * 4] = v4;
        }
        __syncthreads();

#pragma unroll
        for (int kk = 0; kk < BK; kk++) {
            float a[8];
#pragma unroll
            for (int i = 0; i < 8; i++) a[i] = Wts[ty * 8 + i][kk];
            float4 b0 = *(float4*)&Xts[kk][tx * 8];
            float4 b1 = *(float4*)&Xts[kk][tx * 8 + 4];
#pragma unroll
            for (int i = 0; i < 8; i++) {
                acc[i][0] += a[i] * b0.x;
                acc[i][1] += a[i] * b0.y;
                acc[i][2] += a[i] * b0.z;
                acc[i][3] += a[i] * b0.w;
                acc[i][4] += a[i] * b1.x;
                acc[i][5] += a[i] * b1.y;
                acc[i][6] += a[i] * b1.z;
                acc[i][7] += a[i] * b1.w;
            }
        }
    }

    float* outp = g_qk + (size_t)b * Cc * Nn;
#pragma unroll
    for (int i = 0; i < 8; i++) {
        int row = o0 + ty * 8 + i;
        float* rp = outp + (size_t)row * Nn + n0 + tx * 8;
        *(float4*)rp       = make_float4(acc[i][0], acc[i][1], acc[i][2], acc[i][3]);
        *(float4*)(rp + 4) = make_float4(acc[i][4], acc[i][5], acc[i][6], acc[i][7]);
    }
}

// ======================= K2: depthwise 3x3x3 conv ===========================
// block = (h, c, b); 192 threads; thread handles one (w, 12-d strip).
__global__ __launch_bounds__(192) void k_conv_v(const float* __restrict__ x,
                                                const float* __restrict__ Wv,
                                                const float* __restrict__ bv) {
    __shared__ float xs[3][48][48];   // h-1, h, h+1 planes (27 KB)
    const int h = blockIdx.x, c = blockIdx.y, b = blockIdx.z;
    const float* xc = x + ((size_t)b * Cc + c) * Nn;
    const int tid = threadIdx.x;

    for (int i = tid; i < 3 * PLANE; i += 192) {
        int hh = i / PLANE;
        int rem = i - hh * PLANE;
        int hg = h + hh - 1;
        ((float*)xs)[i] = (hg >= 0 && hg < Hh) ? xc[(size_t)hg * PLANE + rem] : 0.f;
    }
    float wv[27];
#pragma unroll
    for (int i = 0; i < 27; i++) wv[i] = Wv[c * 27 + i];
    const float bias = bv[c];
    __syncthreads();

    const int w  = tid >> 2;
    const int d0 = (tid & 3) * 12;

    float o[12];
#pragma unroll
    for (int j = 0; j < 12; j++) o[j] = bias;

#pragma unroll
    for (int hh = 0; hh < 3; hh++) {
#pragma unroll
        for (int ww = 0; ww < 3; ww++) {
            int wg = w + ww - 1;
            if (wg < 0 || wg >= 48) continue;
            const float* row = xs[hh][wg];
            const float w0 = wv[(hh * 3 + ww) * 3 + 0];
            const float w1 = wv[(hh * 3 + ww) * 3 + 1];
            const float w2 = wv[(hh * 3 + ww) * 3 + 2];
            float xm = (d0 > 0) ? row[d0 - 1] : 0.f;
            float x0 = row[d0];
#pragma unroll
            for (int j = 0; j < 12; j++) {
                int d = d0 + j;
                float xp = (d + 1 < 48) ? row[d + 1] : 0.f;
                o[j] += w0 * xm + w1 * x0 + w2 * xp;
                xm = x0; x0 = xp;
            }
        }
    }

    float* vp = g_v + ((size_t)b * Cc + c) * Nn + (size_t)h * PLANE + w * 48 + d0;
#pragma unroll
    for (int q = 0; q < 3; q++)
        *(float4*)(vp + q * 4) = make_float4(o[q*4], o[q*4+1], o[q*4+2], o[q*4+3]);
}

// ======================= zero accumulators ===========================
__global__ void k_zero() {
    int i = blockIdx.x * 256 + threadIdx.x;
    if (i < Bb * NH * DQK * DV) g_kv[i] = 0.f;
    if (i < Bb * NH * DQK) g_s[i] = 0.f;
}

// ======================= K3: kv reduction ===========================
// kv[dk][dv] += exp(k[dk][n]) * v[dv][n]; s[dk] += exp(k[dk][n])
__global__ __launch_bounds__(256) void k_kv_reduce() {
    __shared__ float es[DQK][68];
    __shared__ float vs[DV][68];
    const int b = blockIdx.z, head = blockIdx.y;
    const int nbase = blockIdx.x * 1728;
    const float* kp = g_qk + ((size_t)b * Cc + QKD + head * DQK) * Nn;
    const float* vp = g_v  + ((size_t)b * Cc + head * DV) * Nn;
    const int tid = threadIdx.x;
    const int dv = tid & 63, dkg = tid >> 6;  // thread owns dk = dkg*8+i, this dv

    float acc[8];
    float sp[8];
#pragma unroll
    for (int i = 0; i < 8; i++) { acc[i] = 0.f; sp[i] = 0.f; }

    for (int t = 0; t < 27; t++) {
        int n0 = nbase + t * 64;
        __syncthreads();
#pragma unroll
        for (int u = 0; u < 8; u++) {           // 32x64 exp(k) tile
            int dk = u * 4 + (tid >> 6);
            int j = tid & 63;
            float e = __expf(kp[(size_t)dk * Nn + n0 + j]);
            es[dk][j] = e;
            sp[u] += e;
        }
#pragma unroll
        for (int u = 0; u < 16; u++) {          // 64x64 v tile
            int r = u * 4 + (tid >> 6);
            int j = tid & 63;
            vs[r][j] = vp[(size_t)r * Nn + n0 + j];
        }
        __syncthreads();
#pragma unroll
        for (int jt = 0; jt < 16; jt++) {
            float4 v4 = *(float4*)&vs[dv][jt * 4];
#pragma unroll
            for (int i = 0; i < 8; i++) {
                float4 e4 = *(float4*)&es[dkg * 8 + i][jt * 4];
                acc[i] += e4.x * v4.x + e4.y * v4.y + e4.z * v4.z + e4.w * v4.w;
            }
        }
    }

    float* kvp = g_kv + (size_t)((b * NH + head) * DQK) * DV;
#pragma unroll
    for (int i = 0; i < 8; i++)
        atomicAdd(&kvp[(dkg * 8 + i) * DV + dv], acc[i]);
    float* spg = g_s + (b * NH + head) * DQK;
#pragma unroll
    for (int u = 0; u < 8; u++)
        atomicAdd(&spg[u * 4 + (tid >> 6)], sp[u]);
}

// ======================= K4: normalize kv ===========================
__global__ void k_kvnorm() {
    int i = blockIdx.x * 256 + threadIdx.x;
    if (i < Bb * NH * DQK * DV)
        g_kvn[i] = g_kv[i] / g_s[i / DV];
}

// ======================= K5: q softmax + matvec -> out ===========================
__global__ __launch_bounds__(256) void k_final(float* __restrict__ out) {
    __shared__ float kvs[NH][DQK][DV];   // 32 KB
    const int b = blockIdx.y;
    const int n = blockIdx.x * 256 + threadIdx.x;
    for (int i = threadIdx.x; i < NH * DQK * DV; i += 256)
        ((float*)kvs)[i] = g_kvn[b * NH * DQK * DV + i];
    __syncthreads();

    const float* qp = g_qk + (size_t)b * Cc * Nn;
    float* op = out + (size_t)b * Cc * Nn;
    const float inv1e = 1.f / (1.f + EPSILON);

#pragma unroll 1
    for (int head = 0; head < NH; head++) {
        float e[DQK];
        float ssum = 0.f;
#pragma unroll
        for (int dk = 0; dk < DQK; dk++) {
            e[dk] = __expf(qp[(size_t)(head * DQK + dk) * Nn + n]);
            ssum += e[dk];
        }
        const float scale = inv1e / ssum;
#pragma unroll
        for (int dvg = 0; dvg < 16; dvg++) {
            float4 a = make_float4(0.f, 0.f, 0.f, 0.f);
#pragma unroll
            for (int dk = 0; dk < DQK; dk++) {
                float4 kv4 = *(float4*)&kvs[head][dk][dvg * 4];
                a.x += e[dk] * kv4.x;
                a.y += e[dk] * kv4.y;
                a.z += e[dk] * kv4.z;
                a.w += e[dk] * kv4.w;
            }
            int c = head * DV + dvg * 4;
            op[(size_t)(c + 0) * Nn + n] = a.x * scale;
            op[(size_t)(c + 1) * Nn + n] = a.y * scale;
            op[(size_t)(c + 2) * Nn + n] = a.z * scale;
            op[(size_t)(c + 3) * Nn + n] = a.w * scale;
        }
    }
}

// ======================= launch ===========================
extern "C" void kernel_launch(void* const* d_in, const int* in_sizes, int n_in,
                              void* d_out, int out_size) {
    const float* x  = (const float*)d_in[0];
    const float* Wq = (const float*)d_in[1];
    const float* Wk = (const float*)d_in[2];
    const float* Wv = (const float*)d_in[3];
    const float* bv = (const float*)d_in[4];
    float* out = (float*)d_out;

    k_gemm_qk<<<dim3(Nn / BN, Cc / BM, Bb), 256>>>(x, Wq, Wk);
    k_conv_v<<<dim3(Hh, Cc, Bb), 192>>>(x, Wv, bv);
    k_zero<<<64, 256>>>();
    k_kv_reduce<<<dim3(64, NH, Bb), 256>>>();
    k_kvnorm<<<64, 256>>>();
    k_final<<<dim3(Nn / 256, Bb), 256>>>(out);
}

// round 2
// speedup vs baseline: 1.1941x; 1.1941x over previous
#include <cuda_runtime.h>
#include <cuda_bf16.h>

#define Bb 2
#define Cc 256
#define Hh 48
#define Nn 110592        // 48*48*48
#define PLANE 2304       // 48*48
#define NH 4
#define DV 64
#define DQK 32
#define QKD 128
#define EPSILON 1e-6f

typedef unsigned long long ull;

__device__ __forceinline__ void fma2(ull& d, ull a, ull b) {
    asm("fma.rn.f32x2 %0, %1, %2, %0;" : "+l"(d) : "l"(a), "l"(b));
}
__device__ __forceinline__ ull pack2(float lo, float hi) {
    ull r; asm("mov.b64 %0, {%1, %2};" : "=l"(r) : "f"(lo), "f"(hi)); return r;
}
__device__ __forceinline__ float2 unpack2(ull v) {
    float lo, hi; asm("mov.b64 {%0, %1}, %2;" : "=f"(lo), "=f"(hi) : "l"(v));
    return make_float2(lo, hi);
}
union F4U2 { float4 f4; ull u2[2]; };

// -------- scratch (static device globals; no allocation at runtime) --------
__device__ __align__(16) float g_qk[(size_t)Bb * Cc * Nn];   // rows 0..127 = q logits, 128..255 = k logits
__device__ __align__(16) float g_v[(size_t)Bb * Cc * Nn];    // depthwise conv output
__device__ float g_kv[Bb * NH * DQK * DV];                   // unnormalized kv
__device__ float g_s[Bb * NH * DQK];                         // sum of exp(k) per dk row
__device__ float g_kvn[Bb * NH * DQK * DV];                  // normalized kv

// ======================= K1: qk GEMM (FFMA2, double-buffered) ==============
// qk[b][o][n] = sum_c W[o][c] * x[b][c][n]; W = Wq (blockIdx.y==0) / Wk
#define BM 128
#define BN 128
#define BK 16

__global__ __launch_bounds__(256) void k_gemm_qk(const float* __restrict__ x,
                                                 const float* __restrict__ Wq,
                                                 const float* __restrict__ Wk) {
    __shared__ __align__(16) float Wts[2][BM][BK + 4];
    __shared__ __align__(16) float Xts[2][BK][BN];

    const int b  = blockIdx.z;
    const int n0 = blockIdx.x * BN;
    const float* Wsrc = (blockIdx.y == 0) ? Wq : Wk;
    const float* xb = x + (size_t)b * Cc * Nn;

    const int tid = threadIdx.x;
    const int tx = tid & 15;   // n sub-tile
    const int ty = tid >> 4;   // o sub-tile

    float4 wst[2], xst[2];

    auto ldtile = [&](int k0) {
#pragma unroll
        for (int u = 0; u < 2; u++) {
            int idx = u * 256 + tid;
            wst[u] = *(const float4*)(Wsrc + (size_t)(idx >> 2) * Cc + k0 + (idx & 3) * 4);
            xst[u] = *(const float4*)(xb + (size_t)(k0 + (idx >> 5)) * Nn + n0 + (idx & 31) * 4);
        }
    };
    auto sttile = [&](int buf) {
#pragma unroll
        for (int u = 0; u < 2; u++) {
            int idx = u * 256 + tid;
            *(float4*)&Wts[buf][idx >> 2][(idx & 3) * 4] = wst[u];
            *(float4*)&Xts[buf][idx >> 5][(idx & 31) * 4] = xst[u];
        }
    };

    ull acc2[8][4];
#pragma unroll
    for (int i = 0; i < 8; i++)
#pragma unroll
        for (int p = 0; p < 4; p++) acc2[i][p] = 0ull;

    ldtile(0);
    sttile(0);
    __syncthreads();

    for (int t = 0; t < Cc / BK; t++) {
        const int cur = t & 1;
        if (t < Cc / BK - 1) ldtile((t + 1) * BK);

#pragma unroll
        for (int kk = 0; kk < BK; kk++) {
            ull b2[4];
#pragma unroll
            for (int p = 0; p < 4; p++)
                b2[p] = *(ull*)&Xts[cur][kk][tx * 8 + p * 2];
#pragma unroll
            for (int i = 0; i < 8; i++) {
                float a = Wts[cur][ty * 8 + i][kk];
                ull a2 = pack2(a, a);
#pragma unroll
                for (int p = 0; p < 4; p++) fma2(acc2[i][p], a2, b2[p]);
            }
        }

        if (t < Cc / BK - 1) sttile(cur ^ 1);
        __syncthreads();
    }

    const int o0 = blockIdx.y * BM;
    float* outp = g_qk + (size_t)b * Cc * Nn;
#pragma unroll
    for (int i = 0; i < 8; i++) {
        int row = o0 + ty * 8 + i;
        float* rp = outp + (size_t)row * Nn + n0 + tx * 8;
        float2 c0 = unpack2(acc2[i][0]);
        float2 c1 = unpack2(acc2[i][1]);
        float2 c2 = unpack2(acc2[i][2]);
        float2 c3 = unpack2(acc2[i][3]);
        *(float4*)rp       = make_float4(c0.x, c0.y, c1.x, c1.y);
        *(float4*)(rp + 4) = make_float4(c2.x, c2.y, c3.x, c3.y);
    }
}

// ======================= K2: depthwise 3x3x3 conv ===========================
__global__ __launch_bounds__(192) void k_conv_v(const float* __restrict__ x,
                                                const float* __restrict__ Wv,
                                                const float* __restrict__ bv) {
    __shared__ float xs[3][48][48];
    const int h = blockIdx.x, c = blockIdx.y, b = blockIdx.z;
    const float* xc = x + ((size_t)b * Cc + c) * Nn;
    const int tid = threadIdx.x;

    for (int i = tid; i < 3 * PLANE; i += 192) {
        int hh = i / PLANE;
        int rem = i - hh * PLANE;
        int hg = h + hh - 1;
        ((float*)xs)[i] = (hg >= 0 && hg < Hh) ? xc[(size_t)hg * PLANE + rem] : 0.f;
    }
    float wv[27];
#pragma unroll
    for (int i = 0; i < 27; i++) wv[i] = Wv[c * 27 + i];
    const float bias = bv[c];
    __syncthreads();

    const int w  = tid >> 2;
    const int d0 = (tid & 3) * 12;

    float o[12];
#pragma unroll
    for (int j = 0; j < 12; j++) o[j] = bias;

#pragma unroll
    for (int hh = 0; hh < 3; hh++) {
#pragma unroll
        for (int ww = 0; ww < 3; ww++) {
            int wg = w + ww - 1;
            if (wg < 0 || wg >= 48) continue;
            const float* row = xs[hh][wg];
            const float w0 = wv[(hh * 3 + ww) * 3 + 0];
            const float w1 = wv[(hh * 3 + ww) * 3 + 1];
            const float w2 = wv[(hh * 3 + ww) * 3 + 2];
            float xm = (d0 > 0) ? row[d0 - 1] : 0.f;
            float x0 = row[d0];
#pragma unroll
            for (int j = 0; j < 12; j++) {
                int d = d0 + j;
                float xp = (d + 1 < 48) ? row[d + 1] : 0.f;
                o[j] += w0 * xm + w1 * x0 + w2 * xp;
                xm = x0; x0 = xp;
            }
        }
    }

    float* vp = g_v + ((size_t)b * Cc + c) * Nn + (size_t)h * PLANE + w * 48 + d0;
#pragma unroll
    for (int q = 0; q < 3; q++)
        *(float4*)(vp + q * 4) = make_float4(o[q*4], o[q*4+1], o[q*4+2], o[q*4+3]);
}

// ======================= zero accumulators ===========================
__global__ void k_zero() {
    int i = blockIdx.x * 256 + threadIdx.x;
    if (i < Bb * NH * DQK * DV) g_kv[i] = 0.f;
    if (i < Bb * NH * DQK) g_s[i] = 0.f;
}

// ======================= K3: kv reduction (pipelined, conflict-free, FFMA2) =
// kv[dk][dv] += exp(k[dk][n]) * v[dv][n]; s[dk] += exp(k[dk][n])
__global__ __launch_bounds__(256) void k_kv_reduce() {
    __shared__ __align__(16) float es[2][DQK][68];     // e tile, row-major
    __shared__ __align__(16) float vst[2][64][65];     // v tile TRANSPOSED [col][dv]
    const int b = blockIdx.z, head = blockIdx.y;
    const int nbase = blockIdx.x * 1728;
    const float* kp = g_qk + ((size_t)b * Cc + QKD + head * DQK) * Nn;
    const float* vp = g_v  + ((size_t)b * Cc + head * DV) * Nn;
    const int tid = threadIdx.x;
    const int col = tid & 63;      // column within 64-wide tile / also this thread's dv
    const int row4 = tid >> 6;     // 0..3 (load row group / dk octet)
    const int dv = col, dkg = row4;

    float kreg[8], vreg[16], sp[8];
    ull acc2[8];
#pragma unroll
    for (int i = 0; i < 8; i++) { acc2[i] = 0ull; sp[i] = 0.f; }

    auto ldt = [&](int t) {
        const int n0 = nbase + t * 64;
#pragma unroll
        for (int u = 0; u < 8; u++)
            kreg[u] = kp[(size_t)(u * 4 + row4) * Nn + n0 + col];
#pragma unroll
        for (int u = 0; u < 16; u++)
            vreg[u] = vp[(size_t)(u * 4 + row4) * Nn + n0 + col];
    };
    auto stt = [&](int buf) {
#pragma unroll
        for (int u = 0; u < 8; u++) {
            float e = __expf(kreg[u]);
            es[buf][u * 4 + row4][col] = e;
            sp[u] += e;
        }
#pragma unroll
        for (int u = 0; u < 16; u++)
            vst[buf][col][u * 4 + row4] = vreg[u];   // conflict-free: bank=(65*col+row)%32
    };

    ldt(0);
    stt(0);
    __syncthreads();

    for (int t = 0; t < 27; t++) {
        const int cur = t & 1;
        if (t < 26) ldt(t + 1);          // global loads in flight during compute

#pragma unroll
        for (int j = 0; j < 64; j += 4) {
            ull v01 = pack2(vst[cur][j][dv],     vst[cur][j + 1][dv]);
            ull v23 = pack2(vst[cur][j + 2][dv], vst[cur][j + 3][dv]);
#pragma unroll
            for (int i = 0; i < 8; i++) {
                F4U2 e; e.f4 = *(float4*)&es[cur][dkg * 8 + i][j];   // broadcast LDS.128
                fma2(acc2[i], e.u2[0], v01);
                fma2(acc2[i], e.u2[1], v23);
            }
        }

        if (t < 26) stt(cur ^ 1);
        __syncthreads();
    }

    float* kvp = g_kv + (size_t)((b * NH + head) * DQK) * DV;
#pragma unroll
    for (int i = 0; i < 8; i++) {
        float2 aa = unpack2(acc2[i]);
        atomicAdd(&kvp[(dkg * 8 + i) * DV + dv], aa.x + aa.y);
    }
    float* spg = g_s + (b * NH + head) * DQK;
#pragma unroll
    for (int u = 0; u < 8; u++) {
        float s = sp[u];
#pragma unroll
        for (int o = 16; o; o >>= 1) s += __shfl_down_sync(0xffffffffu, s, o);
        if ((tid & 31) == 0) atomicAdd(&spg[u * 4 + row4], s);
    }
}

// ======================= K4: normalize kv ===========================
__global__ void k_kvnorm() {
    int i = blockIdx.x * 256 + threadIdx.x;
    if (i < Bb * NH * DQK * DV)
        g_kvn[i] = g_kv[i] / g_s[i / DV];
}

// ======================= K5: q softmax + matvec -> out (FFMA2) =============
__global__ __launch_bounds__(256) void k_final(float* __restrict__ out) {
    __shared__ __align__(16) float kvs[NH][DQK][DV];   // 32 KB
    const int b = blockIdx.y;
    const int n = blockIdx.x * 256 + threadIdx.x;
    for (int i = threadIdx.x; i < NH * DQK * DV; i += 256)
        ((float*)kvs)[i] = g_kvn[b * NH * DQK * DV + i];
    __syncthreads();

    const float* qp = g_qk + (size_t)b * Cc * Nn;
    float* op = out + (size_t)b * Cc * Nn;
    const float inv1e = 1.f / (1.f + EPSILON);

#pragma unroll 1
    for (int head = 0; head < NH; head++) {
        float e[DQK];
        float ssum = 0.f;
#pragma unroll
        for (int dk = 0; dk < DQK; dk++) {
            e[dk] = __expf(qp[(size_t)(head * DQK + dk) * Nn + n]);
            ssum += e[dk];
        }
        const float scale = inv1e / ssum;
        ull e2[DQK];
#pragma unroll
        for (int dk = 0; dk < DQK; dk++) {
            float s = e[dk] * scale;
            e2[dk] = pack2(s, s);
        }
#pragma unroll 1
        for (int dvg = 0; dvg < 8; dvg++) {          // 8 dv channels per iter
            ull a2[4] = {0ull, 0ull, 0ull, 0ull};
#pragma unroll
            for (int dk = 0; dk < DQK; dk++) {
                F4U2 ka, kb;
                ka.f4 = *(float4*)&kvs[head][dk][dvg * 8];
                kb.f4 = *(float4*)&kvs[head][dk][dvg * 8 + 4];
                fma2(a2[0], e2[dk], ka.u2[0]);
                fma2(a2[1], e2[dk], ka.u2[1]);
                fma2(a2[2], e2[dk], kb.u2[0]);
                fma2(a2[3], e2[dk], kb.u2[1]);
            }
            const int c = head * DV + dvg * 8;
#pragma unroll
            for (int p = 0; p < 4; p++) {
                float2 r = unpack2(a2[p]);
                op[(size_t)(c + 2 * p)     * Nn + n] = r.x;
                op[(size_t)(c + 2 * p + 1) * Nn + n] = r.y;
            }
        }
    }
}

// ======================= launch ===========================
extern "C" void kernel_launch(void* const* d_in, const int* in_sizes, int n_in,
                              void* d_out, int out_size) {
    const float* x  = (const float*)d_in[0];
    const float* Wq = (const float*)d_in[1];
    const float* Wk = (const float*)d_in[2];
    const float* Wv = (const float*)d_in[3];
    const float* bv = (const float*)d_in[4];
    float* out = (float*)d_out;

    k_gemm_qk<<<dim3(Nn / BN, Cc / BM, Bb), 256>>>(x, Wq, Wk);
    k_conv_v<<<dim3(Hh, Cc, Bb), 192>>>(x, Wv, bv);
    k_zero<<<64, 256>>>();
    k_kv_reduce<<<dim3(64, NH, Bb), 256>>>();
    k_kvnorm<<<64, 256>>>();
    k_final<<<dim3(Nn / 256, Bb), 256>>>(out);
}

// round 7
// speedup vs baseline: 1.9718x; 1.6513x over previous
#include <cuda_runtime.h>
#include <cuda_bf16.h>
#include <cstdint>

#define Bb 2
#define Cc 256
#define Hh 48
#define Nn 110592        // 48*48*48
#define PLANE 2304       // 48*48
#define NH 4
#define DV 64
#define DQK 32
#define QKD 128
#define EPSILON 1e-6f

typedef unsigned long long ull;

__device__ __forceinline__ void fma2(ull& d, ull a, ull b) {
    asm("fma.rn.f32x2 %0, %1, %2, %0;" : "+l"(d) : "l"(a), "l"(b));
}
__device__ __forceinline__ ull pack2(float lo, float hi) {
    ull r; asm("mov.b64 %0, {%1, %2};" : "=l"(r) : "f"(lo), "f"(hi)); return r;
}
__device__ __forceinline__ float2 unpack2(ull v) {
    float lo, hi; asm("mov.b64 {%0, %1}, %2;" : "=f"(lo), "=f"(hi) : "l"(v));
    return make_float2(lo, hi);
}
union F4U2 { float4 f4; ull u2[2]; };

// -------- scratch --------
__device__ __align__(16) float g_qk[(size_t)Bb * Cc * Nn];
__device__ __align__(16) float g_v[(size_t)Bb * Cc * Nn];
__device__ float g_kv[Bb * NH * DQK * DV];
__device__ float g_s[Bb * NH * DQK];
__device__ float g_kvn[Bb * NH * DQK * DV];

__device__ __forceinline__ uint32_t smem_u32(const void* p) {
    uint32_t a;
    asm("{ .reg .u64 t; cvta.to.shared.u64 t, %1; cvt.u32.u64 %0, t; }" : "=r"(a) : "l"(p));
    return a;
}

// ===================== mma.sync helpers (sm_80+ baseline PTX) ==============
__device__ __forceinline__ void ldsm4(uint32_t* r, uint32_t addr) {
    asm volatile("ldmatrix.sync.aligned.m8n8.x4.shared.b16 {%0,%1,%2,%3}, [%4];"
                 : "=r"(r[0]), "=r"(r[1]), "=r"(r[2]), "=r"(r[3]) : "r"(addr));
}
__device__ __forceinline__ void ldsm2t(uint32_t* r, uint32_t addr) {
    asm volatile("ldmatrix.sync.aligned.m8n8.x2.trans.shared.b16 {%0,%1}, [%2];"
                 : "=r"(r[0]), "=r"(r[1]) : "r"(addr));
}
__device__ __forceinline__ void mma_bf16(float* d, const uint32_t* a, const uint32_t* b) {
    asm volatile(
        "mma.sync.aligned.m16n8k16.row.col.f32.bf16.bf16.f32 "
        "{%0,%1,%2,%3}, {%4,%5,%6,%7}, {%8,%9}, {%0,%1,%2,%3};"
        : "+f"(d[0]), "+f"(d[1]), "+f"(d[2]), "+f"(d[3])
        : "r"(a[0]), "r"(a[1]), "r"(a[2]), "r"(a[3]), "r"(b[0]), "r"(b[1]));
}
__device__ __forceinline__ void cvt_hl4(float4 f, uint2& hi, uint2& lo) {
    __nv_bfloat16 hx = __float2bfloat16(f.x), hy = __float2bfloat16(f.y);
    __nv_bfloat16 hz = __float2bfloat16(f.z), hw = __float2bfloat16(f.w);
    __nv_bfloat16 lx = __float2bfloat16(f.x - __bfloat162float(hx));
    __nv_bfloat16 ly = __float2bfloat16(f.y - __bfloat162float(hy));
    __nv_bfloat16 lz = __float2bfloat16(f.z - __bfloat162float(hz));
    __nv_bfloat16 lw = __float2bfloat16(f.w - __bfloat162float(hw));
    hi.x = ((uint32_t)__bfloat16_as_ushort(hy) << 16) | __bfloat16_as_ushort(hx);
    hi.y = ((uint32_t)__bfloat16_as_ushort(hw) << 16) | __bfloat16_as_ushort(hz);
    lo.x = ((uint32_t)__bfloat16_as_ushort(ly) << 16) | __bfloat16_as_ushort(lx);
    lo.y = ((uint32_t)__bfloat16_as_ushort(lw) << 16) | __bfloat16_as_ushort(lz);
}

// ======================= K1: qk GEMM via mma.sync 3xBF16 ===================
// D[o 128][n 128] per CTA; K=256 in 4 chunks of 64, single-buffered smem.
// smem layout (bytes): Ah@0 (128x144), Al@18432, Bh@36864 (64x272), Bl@54272
#define GSM_AL 18432
#define GSM_BH 36864
#define GSM_BL 54272
#define GSM_TOT 71680

__global__ void __launch_bounds__(256, 2) k_gemm_mma(const float* __restrict__ x,
                                                     const float* __restrict__ Wq,
                                                     const float* __restrict__ Wk) {
    extern __shared__ __align__(16) char sm[];
    const int tid = threadIdx.x;
    const int lane = tid & 31, w = tid >> 5;
    const int n0 = blockIdx.x * 128;
    const int mh = blockIdx.y;
    const int b  = blockIdx.z;
    const float* Wsrc = mh ? Wk : Wq;
    const float* xb = x + (size_t)b * Cc * Nn;
    const uint32_t smb = smem_u32(sm);

    const int wm = (w & 1) * 64;       // warp M offset
    const int wn = (w >> 1) * 32;      // warp N offset

    // fragment base addresses (per thread)
    const uint32_t aHi = smb + (wm + (lane & 15)) * 144 + (lane >> 4) * 16;
    const uint32_t aLo = aHi + GSM_AL;
    const uint32_t bHi = smb + GSM_BH + (lane & 15) * 272 + wn * 2;
    const uint32_t bLo = bHi + (GSM_BL - GSM_BH);

    float d[4][4][4];
#pragma unroll
    for (int mt = 0; mt < 4; mt++)
#pragma unroll
        for (int nt = 0; nt < 4; nt++)
#pragma unroll
            for (int r = 0; r < 4; r++) d[mt][nt][r] = 0.f;

    for (int kc = 0; kc < 4; kc++) {
        __syncthreads();
        // load A: 128 rows x 64 c -> 2048 float4, 8 per thread
#pragma unroll
        for (int u = 0; u < 8; u++) {
            int i = u * 256 + tid;
            int row = i >> 4, g = i & 15;
            float4 f = *(const float4*)(Wsrc + (size_t)row * Cc + kc * 64 + g * 4);
            uint2 hi, lo; cvt_hl4(f, hi, lo);
            *(uint2*)(sm + row * 144 + g * 8) = hi;
            *(uint2*)(sm + GSM_AL + row * 144 + g * 8) = lo;
        }
        // load B: 64 krows x 128 n -> 2048 float4, 8 per thread (coalesced)
#pragma unroll
        for (int u = 0; u < 8; u++) {
            int i = u * 256 + tid;
            int kr = i >> 5, ng = i & 31;
            float4 f = *(const float4*)(xb + (size_t)(kc * 64 + kr) * Nn + n0 + ng * 4);
            uint2 hi, lo; cvt_hl4(f, hi, lo);
            *(uint2*)(sm + GSM_BH + kr * 272 + ng * 8) = hi;
            *(uint2*)(sm + GSM_BL + kr * 272 + ng * 8) = lo;
        }
        __syncthreads();

#pragma unroll
        for (int s4 = 0; s4 < 4; s4++) {   // k16 steps within the 64-chunk
            uint32_t ah[4][4], bh[4][2], t2[4][2 > 4 ? 2 : 4];
#pragma unroll
            for (int mt = 0; mt < 4; mt++)
                ldsm4(ah[mt], aHi + mt * (16 * 144) + s4 * 32);
#pragma unroll
            for (int nt = 0; nt < 4; nt++)
                ldsm2t(bh[nt], bHi + s4 * (16 * 272) + nt * 16);
#pragma unroll
            for (int mt = 0; mt < 4; mt++)
#pragma unroll
                for (int nt = 0; nt < 4; nt++)
                    mma_bf16(d[mt][nt], ah[mt], bh[nt]);     // hi*hi
            // b_lo pass
#pragma unroll
            for (int nt = 0; nt < 4; nt++)
                ldsm2t(t2[nt], bLo + s4 * (16 * 272) + nt * 16);
#pragma unroll
            for (int mt = 0; mt < 4; mt++)
#pragma unroll
                for (int nt = 0; nt < 4; nt++)
                    mma_bf16(d[mt][nt], ah[mt], t2[nt]);     // hi*lo
            // a_lo pass (reuse ah regs)
#pragma unroll
            for (int mt = 0; mt < 4; mt++)
                ldsm4(ah[mt], aLo + mt * (16 * 144) + s4 * 32);
#pragma unroll
            for (int mt = 0; mt < 4; mt++)
#pragma unroll
                for (int nt = 0; nt < 4; nt++)
                    mma_bf16(d[mt][nt], ah[mt], bh[nt]);     // lo*hi
        }
    }

    // epilogue: d[mt][nt]: rows wm+mt*16+(lane>>2)(+8), cols wn+nt*8+(lane&3)*2
    float* outp = g_qk + (size_t)(b * Cc + mh * 128) * Nn + n0;
    const int r0 = lane >> 2, c0 = (lane & 3) * 2;
#pragma unroll
    for (int mt = 0; mt < 4; mt++) {
#pragma unroll
        for (int nt = 0; nt < 4; nt++) {
            float* p0 = outp + (size_t)(wm + mt * 16 + r0) * Nn + wn + nt * 8 + c0;
            *(float2*)p0 = make_float2(d[mt][nt][0], d[mt][nt][1]);
            float* p1 = p0 + (size_t)8 * Nn;
            *(float2*)p1 = make_float2(d[mt][nt][2], d[mt][nt][3]);
        }
    }
}

// ======================= K2: depthwise 3x3x3 conv ===========================
__global__ __launch_bounds__(192) void k_conv_v(const float* __restrict__ x,
                                                const float* __restrict__ Wv,
                                                const float* __restrict__ bv) {
    __shared__ float xs[3][48][48];
    const int h = blockIdx.x, c = blockIdx.y, b = blockIdx.z;
    const float* xc = x + ((size_t)b * Cc + c) * Nn;
    const int tid = threadIdx.x;

    for (int i = tid; i < 3 * PLANE; i += 192) {
        int hh = i / PLANE;
        int rem = i - hh * PLANE;
        int hg = h + hh - 1;
        ((float*)xs)[i] = (hg >= 0 && hg < Hh) ? xc[(size_t)hg * PLANE + rem] : 0.f;
    }
    float wv[27];
#pragma unroll
    for (int i = 0; i < 27; i++) wv[i] = Wv[c * 27 + i];
    const float bias = bv[c];
    __syncthreads();

    const int w  = tid >> 2;
    const int d0 = (tid & 3) * 12;

    float o[12];
#pragma unroll
    for (int j = 0; j < 12; j++) o[j] = bias;

#pragma unroll
    for (int hh = 0; hh < 3; hh++) {
#pragma unroll
        for (int ww = 0; ww < 3; ww++) {
            int wg = w + ww - 1;
            if (wg < 0 || wg >= 48) continue;
            const float* row = xs[hh][wg];
            const float w0 = wv[(hh * 3 + ww) * 3 + 0];
            const float w1 = wv[(hh * 3 + ww) * 3 + 1];
            const float w2 = wv[(hh * 3 + ww) * 3 + 2];
            float xm = (d0 > 0) ? row[d0 - 1] : 0.f;
            float x0 = row[d0];
#pragma unroll
            for (int j = 0; j < 12; j++) {
                int d = d0 + j;
                float xp = (d + 1 < 48) ? row[d + 1] : 0.f;
                o[j] += w0 * xm + w1 * x0 + w2 * xp;
                xm = x0; x0 = xp;
            }
        }
    }

    float* vp = g_v + ((size_t)b * Cc + c) * Nn + (size_t)h * PLANE + w * 48 + d0;
#pragma unroll
    for (int q = 0; q < 3; q++)
        *(float4*)(vp + q * 4) = make_float4(o[q*4], o[q*4+1], o[q*4+2], o[q*4+3]);
}

// ======================= zero accumulators ===========================
__global__ void k_zero() {
    int i = blockIdx.x * 256 + threadIdx.x;
    if (i < Bb * NH * DQK * DV) g_kv[i] = 0.f;
    if (i < Bb * NH * DQK) g_s[i] = 0.f;
}

// ======================= K3: kv reduction ===========================
__global__ __launch_bounds__(256) void k_kv_reduce() {
    __shared__ __align__(16) float es[2][DQK][68];
    __shared__ __align__(16) float vst[2][64][65];
    const int b = blockIdx.z, head = blockIdx.y;
    const int nbase = blockIdx.x * 1728;
    const float* kp = g_qk + ((size_t)b * Cc + QKD + head * DQK) * Nn;
    const float* vp = g_v  + ((size_t)b * Cc + head * DV) * Nn;
    const int tid = threadIdx.x;
    const int col = tid & 63;
    const int row4 = tid >> 6;
    const int dv = col, dkg = row4;

    float kreg[8], vreg[16], sp[8];
    ull acc2[8];
#pragma unroll
    for (int i = 0; i < 8; i++) { acc2[i] = 0ull; sp[i] = 0.f; }

    auto ldt = [&](int t) {
        const int n0 = nbase + t * 64;
#pragma unroll
        for (int u = 0; u < 8; u++)
            kreg[u] = kp[(size_t)(u * 4 + row4) * Nn + n0 + col];
#pragma unroll
        for (int u = 0; u < 16; u++)
            vreg[u] = vp[(size_t)(u * 4 + row4) * Nn + n0 + col];
    };
    auto stt = [&](int buf) {
#pragma unroll
        for (int u = 0; u < 8; u++) {
            float e = __expf(kreg[u]);
            es[buf][u * 4 + row4][col] = e;
            sp[u] += e;
        }
#pragma unroll
        for (int u = 0; u < 16; u++)
            vst[buf][col][u * 4 + row4] = vreg[u];
    };

    ldt(0);
    stt(0);
    __syncthreads();

    for (int t = 0; t < 27; t++) {
        const int cur = t & 1;
        if (t < 26) ldt(t + 1);

#pragma unroll
        for (int j = 0; j < 64; j += 4) {
            ull v01 = pack2(vst[cur][j][dv],     vst[cur][j + 1][dv]);
            ull v23 = pack2(vst[cur][j + 2][dv], vst[cur][j + 3][dv]);
#pragma unroll
            for (int i = 0; i < 8; i++) {
                F4U2 e; e.f4 = *(float4*)&es[cur][dkg * 8 + i][j];
                fma2(acc2[i], e.u2[0], v01);
                fma2(acc2[i], e.u2[1], v23);
            }
        }

        if (t < 26) stt(cur ^ 1);
        __syncthreads();
    }

    float* kvp = g_kv + (size_t)((b * NH + head) * DQK) * DV;
#pragma unroll
    for (int i = 0; i < 8; i++) {
        float2 aa = unpack2(acc2[i]);
        atomicAdd(&kvp[(dkg * 8 + i) * DV + dv], aa.x + aa.y);
    }
    float* spg = g_s + (b * NH + head) * DQK;
#pragma unroll
    for (int u = 0; u < 8; u++) {
        float s = sp[u];
#pragma unroll
        for (int o = 16; o; o >>= 1) s += __shfl_down_sync(0xffffffffu, s, o);
        if ((tid & 31) == 0) atomicAdd(&spg[u * 4 + row4], s);
    }
}

// ======================= K4: normalize kv ===========================
__global__ void k_kvnorm() {
    int i = blockIdx.x * 256 + threadIdx.x;
    if (i < Bb * NH * DQK * DV)
        g_kvn[i] = g_kv[i] / g_s[i / DV];
}

// ======================= K5: q softmax + matvec -> out =============
__global__ __launch_bounds__(256) void k_final(float* __restrict__ out) {
    __shared__ __align__(16) float kvs[NH][DQK][DV];
    const int b = blockIdx.y;
    const int n = blockIdx.x * 256 + threadIdx.x;
    for (int i = threadIdx.x; i < NH * DQK * DV; i += 256)
        ((float*)kvs)[i] = g_kvn[b * NH * DQK * DV + i];
    __syncthreads();

    const float* qp = g_qk + (size_t)b * Cc * Nn;
    float* op = out + (size_t)b * Cc * Nn;
    const float inv1e = 1.f / (1.f + EPSILON);

#pragma unroll 1
    for (int head = 0; head < NH; head++) {
        float e[DQK];
        float ssum = 0.f;
#pragma unroll
        for (int dk = 0; dk < DQK; dk++) {
            e[dk] = __expf(qp[(size_t)(head * DQK + dk) * Nn + n]);
            ssum += e[dk];
        }
        const float scale = inv1e / ssum;
        ull e2[DQK];
#pragma unroll
        for (int dk = 0; dk < DQK; dk++) {
            float s = e[dk] * scale;
            e2[dk] = pack2(s, s);
        }
#pragma unroll 1
        for (int dvg = 0; dvg < 8; dvg++) {
            ull a2[4] = {0ull, 0ull, 0ull, 0ull};
#pragma unroll
            for (int dk = 0; dk < DQK; dk++) {
                F4U2 ka, kb;
                ka.f4 = *(float4*)&kvs[head][dk][dvg * 8];
                kb.f4 = *(float4*)&kvs[head][dk][dvg * 8 + 4];
                fma2(a2[0], e2[dk], ka.u2[0]);
                fma2(a2[1], e2[dk], ka.u2[1]);
                fma2(a2[2], e2[dk], kb.u2[0]);
                fma2(a2[3], e2[dk], kb.u2[1]);
            }
            const int c = head * DV + dvg * 8;
#pragma unroll
            for (int p = 0; p < 4; p++) {
                float2 r = unpack2(a2[p]);
                op[(size_t)(c + 2 * p)     * Nn + n] = r.x;
                op[(size_t)(c + 2 * p + 1) * Nn + n] = r.y;
            }
        }
    }
}

// ======================= launch ===========================
extern "C" void kernel_launch(void* const* d_in, const int* in_sizes, int n_in,
                              void* d_out, int out_size) {
    const float* x  = (const float*)d_in[0];
    const float* Wq = (const float*)d_in[1];
    const float* Wk = (const float*)d_in[2];
    const float* Wv = (const float*)d_in[3];
    const float* bv = (const float*)d_in[4];
    float* out = (float*)d_out;

    cudaFuncSetAttribute(k_gemm_mma, cudaFuncAttributeMaxDynamicSharedMemorySize, GSM_TOT);
    k_gemm_mma<<<dim3(Nn / 128, 2, Bb), 256, GSM_TOT>>>(x, Wq, Wk);
    k_conv_v<<<dim3(Hh, Cc, Bb), 192>>>(x, Wv, bv);
    k_zero<<<64, 256>>>();
    k_kv_reduce<<<dim3(64, NH, Bb), 256>>>();
    k_kvnorm<<<64, 256>>>();
    k_final<<<dim3(Nn / 256, Bb), 256>>>(out);
}